// round 15
// baseline (speedup 1.0000x reference)
#include <cuda_runtime.h>
#include <cuda_fp16.h>
#include <cstdint>

#define Hd   1024
#define Bb   16
#define Ss   512
#define Kk   32
#define Ee   1024
#define NCAT 3072

// ---------------- scratch ----------------------------------------------------
__device__ __half g_Xh[512*Hd];          // full_nodes fp16 [512][1024]
__device__ __half g_Wh[Hd*NCAT];         // Wcat fp16 [k][n]
__device__ float g_node_hidden[512*Hd];
__device__ float g_Aj[512*Hd];           // edge bias folded in
__device__ float g_Ai[512*Hd];
__device__ float g_cls_hidden[Bb*Hd];
__device__ float g_invconst[2];
__device__ int   g_n[Bb];

// ---------------- helpers ----------------------------------------------------
__device__ __forceinline__ float tanh_fast(float x) {
    float e = __expf(2.0f * x);
    return 1.0f - __fdividef(2.0f, e + 1.0f);
}

__device__ __forceinline__ uint32_t smem_u32(const void* p) {
    uint32_t a;
    asm("{ .reg .u64 t; cvta.to.shared.u64 t, %1; cvt.u32.u64 %0, t; }" : "=r"(a) : "l"(p));
    return a;
}

__device__ __forceinline__ void cp16(uint32_t saddr, const void* g) {
    asm volatile("cp.async.cg.shared.global [%0], [%1], 16;" :: "r"(saddr), "l"(g));
}
__device__ __forceinline__ void cp_commit() {
    asm volatile("cp.async.commit_group;");
}
template <int N>
__device__ __forceinline__ void cp_wait() {
    asm volatile("cp.async.wait_group %0;" :: "n"(N));
}

__device__ __forceinline__ void ldsm_x4(uint32_t& r0, uint32_t& r1, uint32_t& r2,
                                        uint32_t& r3, uint32_t addr) {
    asm volatile("ldmatrix.sync.aligned.m8n8.x4.shared.b16 {%0,%1,%2,%3}, [%4];"
                 : "=r"(r0), "=r"(r1), "=r"(r2), "=r"(r3) : "r"(addr));
}
__device__ __forceinline__ void ldsm_x2t(uint32_t& r0, uint32_t& r1, uint32_t addr) {
    asm volatile("ldmatrix.sync.aligned.m8n8.x2.trans.shared.b16 {%0,%1}, [%2];"
                 : "=r"(r0), "=r"(r1) : "r"(addr));
}
__device__ __forceinline__ void mma16816h(float* d, const uint32_t* a, const uint32_t* b) {
    asm volatile(
        "mma.sync.aligned.m16n8k16.row.col.f32.f16.f16.f32 "
        "{%0,%1,%2,%3}, {%4,%5,%6,%7}, {%8,%9}, {%0,%1,%2,%3};"
        : "+f"(d[0]), "+f"(d[1]), "+f"(d[2]), "+f"(d[3])
        : "r"(a[0]), "r"(a[1]), "r"(a[2]), "r"(a[3]), "r"(b[0]), "r"(b[1]));
}

__device__ __forceinline__ void block_reduce2(float& a0, float& a1, float* red) {
    #pragma unroll
    for (int o = 16; o > 0; o >>= 1) {
        a0 += __shfl_down_sync(0xffffffffu, a0, o);
        a1 += __shfl_down_sync(0xffffffffu, a1, o);
    }
    int w = threadIdx.x >> 5;
    if ((threadIdx.x & 31) == 0) { red[2*w] = a0; red[2*w+1] = a1; }
    __syncthreads();
    if (threadIdx.x == 0) {
        a0 = red[0]; a1 = red[1];
        for (int w2 = 1; w2 < (int)(blockDim.x >> 5); w2++) {
            a0 += red[2*w2]; a1 += red[2*w2+1];
        }
    }
}

__device__ __forceinline__ void warp_reduce2(float& a0, float& a1) {
    #pragma unroll
    for (int o = 16; o > 0; o >>= 1) {
        a0 += __shfl_down_sync(0xffffffffu, a0, o);
        a1 += __shfl_down_sync(0xffffffffu, a1, o);
    }
}

#define BROW 272

// ======== 1. k_prep — streaming conversions + fused cls GEMVs ===============
// blocks: [0,16) fused naf/cls GEMV; [16,528) meta; [528,1552) Wcat rows;
//         1552 invconst.
__global__ __launch_bounds__(256) void k_prep(const float* __restrict__ seq,
                                              const int* __restrict__ P,
                                              const float* __restrict__ nodeW,
                                              const float* __restrict__ eW,
                                              const float* __restrict__ eb,
                                              const float* __restrict__ eoW,
                                              const float* __restrict__ eob,
                                              const float* __restrict__ nafW,
                                              const float* __restrict__ nafb,
                                              const float* __restrict__ clsW,
                                              const float* __restrict__ clsb) {
    __shared__ __align__(16) char shm[1280 + 32*BROW + 128];   // A | B | misc
    int blk = blockIdx.x;
    int t   = threadIdx.x;

    if (blk < 16) {
        // ---- fused GEMV: out cols [x*128, x*128+128) of [naf | cls] ----
        char* smA = shm;                 // 16 rows x 80B fp16
        char* smB = shm + 1280;          // 32 rows x 272B fp16
        int*  sn  = (int*)(shm + 1280 + 32*BROW);
        int x = blk;
        bool is_cls = x >= 8;
        const float* Wsrc = is_cls ? clsW : nafW;
        const float* bsrc = is_cls ? clsb : nafb;
        int c0 = (x & 7) * 128;
        int wid = t >> 5, lane = t & 31;
        uint32_t smbA = smem_u32(smA);
        uint32_t smbB = smem_u32(smB);

        if (t < 16) {
            int n = 0;
            #pragma unroll
            for (int j = 0; j < Kk - 1; j++) n += (P[t*Kk + 1 + j] > 0);
            sn[t] = n;
        }

        float acc[4][4];
        #pragma unroll
        for (int nt = 0; nt < 4; nt++)
            #pragma unroll
            for (int q = 0; q < 4; q++) acc[nt][q] = 0.0f;

        int brow = (lane & 7) + ((lane >> 3) & 1)*8;

        for (int ch = 0; ch < 32; ch++) {
            __syncthreads();
            // B chunk: 32 k-rows x 128 cols fp32 -> fp16 smem (trans layout)
            #pragma unroll
            for (int f = 0; f < 2; f++) {
                int j = t + f*256;               // 0..511
                int r = j >> 4, cs = j & 15;     // 16 segs of 8 cols
                const float* src = &Wsrc[(long)(ch*32 + r)*Hd + c0 + cs*8];
                float4 u = *(const float4*)src;
                float4 v = *(const float4*)(src + 4);
                uint4 o;
                *(__half2*)&o.x = __floats2half2_rn(u.x, u.y);
                *(__half2*)&o.y = __floats2half2_rn(u.z, u.w);
                *(__half2*)&o.z = __floats2half2_rn(v.x, v.y);
                *(__half2*)&o.w = __floats2half2_rn(v.z, v.w);
                *(uint4*)(smB + r*BROW + cs*16) = o;
            }
            // A chunk: 16 batch rows x 32 k fp32 -> fp16 smem
            if (t < 64) {
                int row = t >> 2, kk = t & 3;    // 4 segs of 8
                const float* src = &seq[(long)row*Ss*Hd + ch*32 + kk*8];
                float4 u = *(const float4*)src;
                float4 v = *(const float4*)(src + 4);
                uint4 o;
                *(__half2*)&o.x = __floats2half2_rn(u.x, u.y);
                *(__half2*)&o.y = __floats2half2_rn(u.z, u.w);
                *(__half2*)&o.z = __floats2half2_rn(v.x, v.y);
                *(__half2*)&o.w = __floats2half2_rn(v.z, v.w);
                *(uint4*)(smA + row*80 + kk*16) = o;
            }
            __syncthreads();
            if (t < 128) {
                #pragma unroll
                for (int ks = 0; ks < 2; ks++) {
                    uint32_t a[4];
                    uint32_t ao = (uint32_t)((lane & 15)*80 + ks*32 + (lane >> 4)*16);
                    ldsm_x4(a[0], a[1], a[2], a[3], smbA + ao);
                    #pragma unroll
                    for (int nt = 0; nt < 4; nt++) {
                        uint32_t bo = (uint32_t)((ks*16 + brow)*BROW + wid*64 + nt*16);
                        uint32_t b0, b1;
                        ldsm_x2t(b0, b1, smbB + bo);
                        uint32_t bf[2] = {b0, b1};
                        mma16816h(acc[nt], a, bf);
                    }
                }
            }
        }
        __syncthreads();
        if (t < 128) {
            int g = lane >> 2, tt = lane & 3;
            #pragma unroll
            for (int nt = 0; nt < 4; nt++) {
                int col = c0 + wid*32 + nt*8 + tt*2;
                #pragma unroll
                for (int half = 0; half < 2; half++) {
                    int b = g + half*8;
                    float v0 = acc[nt][half*2 + 0] + bsrc[col];
                    float v1 = acc[nt][half*2 + 1] + bsrc[col+1];
                    if (!is_cls) {
                        int slot = sn[b];
                        *(__half2*)&g_Xh[(long)(b*Kk + slot)*Hd + col] =
                            __floats2half2_rn(v0, v1);
                    } else {
                        g_cls_hidden[b*Hd + col]     = tanh_fast(v0);
                        g_cls_hidden[b*Hd + col + 1] = tanh_fast(v1);
                    }
                }
            }
        }
        return;
    }

    if (blk < 528) {
        // ---- meta: segment mean (b,k); row k==n written by GEMV blocks ----
        int kb = blk - 16;
        int k = kb & 31, b = kb >> 5;
        int n = 0;
        #pragma unroll
        for (int j = 0; j < Kk - 1; j++) n += (P[b*Kk + 1 + j] > 0);
        if (k == 0 && t == 0) g_n[b] = n;
        long row = (long)(b*Kk + k) * Hd;
        if (k < n) {
            int end   = P[b*Kk + 1 + k];
            int start = (k == 0) ? 1 : (P[b*Kk + k] + 1);
            float inv = 1.0f / (float)(end - start + 1);
            #pragma unroll
            for (int u = 0; u < Hd/256; u++) {
                int h = t + u*256;
                float s = 0.0f;
                for (int p = start; p <= end; p++)
                    s += seq[((long)b*Ss + p)*Hd + h];
                g_Xh[row + h] = __float2half(s * inv);
            }
        } else if (k > n) {
            #pragma unroll
            for (int u = 0; u < Hd/256; u++)
                g_Xh[row + t + u*256] = __float2half(0.f);
        }
        return;
    }

    if (blk < 1552) {
        // ---- Wcat row k: [node | W0+W2 | W1-W2], fp16, [k][n] layout ----
        int k = blk - 528;
        const float* nw = nodeW + (long)k*Hd;
        const float* e0 = eW + (long)k*Hd;
        const float* e1 = eW + (long)(Hd + k)*Hd;
        const float* e2 = eW + (long)(2*Hd + k)*Hd;
        __half* dst = g_Wh + (long)k*NCAT;
        #pragma unroll
        for (int i = t*2; i < Hd; i += 512) {
            float2 a = *(const float2*)&nw[i];
            float2 b0 = *(const float2*)&e0[i];
            float2 b1 = *(const float2*)&e1[i];
            float2 b2 = *(const float2*)&e2[i];
            *(__half2*)&dst[i]        = __floats2half2_rn(a.x, a.y);
            *(__half2*)&dst[Hd + i]   = __floats2half2_rn(b0.x + b2.x, b0.y + b2.y);
            *(__half2*)&dst[2*Hd + i] = __floats2half2_rn(b1.x - b2.x, b1.y - b2.y);
        }
        return;
    }

    // ---- invalid-edge constant ----
    {
        float* red = (float*)shm;
        float a0 = 0.f, a1 = 0.f;
        #pragma unroll
        for (int u = 0; u < Hd/256; u++) {
            int h = t + u*256;
            float v = tanh_fast(eb[h]);
            a0 = fmaf(v, eoW[2*h  ], a0);
            a1 = fmaf(v, eoW[2*h+1], a1);
        }
        block_reduce2(a0, a1, red);
        if (t == 0) { g_invconst[0] = a0 + eob[0]; g_invconst[1] = a1 + eob[1]; }
    }
}

// ======== 2. fp16 tensor GEMM, trans-B, 4-stage cp.async ====================
#define A_OFF 0
#define B_OFF 5120
#define STAGE_B (5120 + 32*BROW)
__global__ __launch_bounds__(128) void k_gemm(const float* __restrict__ node_b,
                                              const float* __restrict__ edge_b) {
    extern __shared__ __align__(16) char sm[];

    int tid  = threadIdx.x;
    int wid  = tid >> 5, lane = tid & 31;
    int wm   = wid & 1;
    int wn   = wid >> 1;
    int bn   = blockIdx.x, bm = blockIdx.y;

    const char* gX = (const char*)g_Xh + (long)bm*64*2048;
    const char* gW = (const char*)g_Wh + bn*256;
    uint32_t smb = smem_u32(sm);

    auto load_stage = [&](int ch, int st) {
        uint32_t sb = smb + st*STAGE_B;
        #pragma unroll
        for (int i = 0; i < 6; i++) {
            int idx = tid + i*128;
            if (idx < 256) {
                int r = idx >> 2, c = (idx & 3)*16;
                cp16(sb + A_OFF + r*80 + c, gX + (long)r*2048 + ch*64 + c);
            } else {
                int j = idx - 256;
                int r = j >> 4, c = (j & 15)*16;
                cp16(sb + B_OFF + r*BROW + c, gW + (long)(ch*32 + r)*6144 + c);
            }
        }
    };

    float acc[2][8][4];
    #pragma unroll
    for (int mt = 0; mt < 2; mt++)
        #pragma unroll
        for (int nt = 0; nt < 8; nt++)
            #pragma unroll
            for (int q = 0; q < 4; q++) acc[mt][nt][q] = 0.0f;

    int a_row  = wm*32 + (lane & 15);
    int a_koff = (lane >> 4) * 16;
    int brow   = (lane & 7) + ((lane >> 3) & 1)*8;

    load_stage(0, 0); cp_commit();
    load_stage(1, 1); cp_commit();
    load_stage(2, 2); cp_commit();

    for (int ch = 0; ch < 32; ch++) {
        cp_wait<2>();
        __syncthreads();
        uint32_t sbase = smb + (ch & 3)*STAGE_B;

        #pragma unroll
        for (int ks = 0; ks < 2; ks++) {
            uint32_t a[2][4];
            #pragma unroll
            for (int mt = 0; mt < 2; mt++) {
                uint32_t ao = (uint32_t)((a_row + mt*16)*80 + ks*32 + a_koff);
                ldsm_x4(a[mt][0], a[mt][1], a[mt][2], a[mt][3], sbase + A_OFF + ao);
            }
            #pragma unroll
            for (int nt = 0; nt < 8; nt++) {
                uint32_t bo = (uint32_t)((ks*16 + brow)*BROW + (wn*64 + nt*8)*2);
                uint32_t b0, b1;
                ldsm_x2t(b0, b1, sbase + B_OFF + bo);
                uint32_t bf[2] = {b0, b1};
                #pragma unroll
                for (int mt = 0; mt < 2; mt++)
                    mma16816h(acc[mt][nt], a[mt], bf);
            }
        }
        if (ch + 3 < 32) load_stage(ch + 3, (ch + 3) & 3);
        cp_commit();
    }

    // ---- epilogue: fp32 outputs ----
    int g = lane >> 2, t = lane & 3;
    int region = bn >> 3;
    #pragma unroll
    for (int mt = 0; mt < 2; mt++) {
        #pragma unroll
        for (int nt = 0; nt < 8; nt++) {
            int col = bn*128 + wn*64 + nt*8 + t*2;
            #pragma unroll
            for (int half = 0; half < 2; half++) {
                int row = bm*64 + wm*32 + mt*16 + g + half*8;
                float v0 = acc[mt][nt][half*2 + 0];
                float v1 = acc[mt][nt][half*2 + 1];
                if (region == 0) {
                    float2 o = make_float2(tanh_fast(v0 + node_b[col]),
                                           tanh_fast(v1 + node_b[col+1]));
                    *(float2*)&g_node_hidden[(long)row*Hd + col] = o;
                } else if (region == 1) {
                    int h = col - Hd;
                    float2 o = make_float2(v0 + edge_b[h], v1 + edge_b[h+1]);
                    *(float2*)&g_Aj[(long)row*Hd + h] = o;
                } else {
                    int h = col - 2*Hd;
                    *(float2*)&g_Ai[(long)row*Hd + h] = make_float2(v0, v1);
                }
            }
        }
    }
}

// ======== 3. k_post: heads + invalid fill + 2-edge-per-warp logits ==========
// blocks: [0,66) heads; [66,82) invalid fill; [82, 82+1024) edge groups of 16.
__global__ __launch_bounds__(256) void k_post(const float* __restrict__ clsoW,
                                              const float* __restrict__ clsob,
                                              const float* __restrict__ noW,
                                              const float* __restrict__ nob,
                                              const float* __restrict__ eoW,
                                              const float* __restrict__ eob,
                                              float* __restrict__ out) {
    __shared__ __half2 sWh[Hd];      // packed (w0,w1) per h, 4 KB
    int blk = blockIdx.x;
    int tid = threadIdx.x;
    int wid = tid >> 5, lane = tid & 31;
    const long EBASE = 32 + Bb*Kk*2;

    if (blk < 66) {
        int r = blk*8 + wid;           // 0..527
        float a0 = 0.f, a1 = 0.f;
        const float *src, *oW, *ob;
        long obase;
        if (r < 16) { src = g_cls_hidden + (long)r*Hd; oW = clsoW; ob = clsob; obase = r*2; }
        else { int rr = r - 16; src = g_node_hidden + (long)rr*Hd; oW = noW; ob = nob; obase = 32 + rr*2; }
        #pragma unroll
        for (int s = 0; s < 8; s++) {
            int h = s*128 + lane*4;
            float4 v  = *(const float4*)&src[h];
            float4 wa = *(const float4*)&oW[2*h];
            float4 wb = *(const float4*)&oW[2*h + 4];
            a0 = fmaf(v.x, wa.x, a0); a1 = fmaf(v.x, wa.y, a1);
            a0 = fmaf(v.y, wa.z, a0); a1 = fmaf(v.y, wa.w, a1);
            a0 = fmaf(v.z, wb.x, a0); a1 = fmaf(v.z, wb.y, a1);
            a0 = fmaf(v.w, wb.z, a0); a1 = fmaf(v.w, wb.w, a1);
        }
        warp_reduce2(a0, a1);
        if (lane == 0) { out[obase] = a0 + ob[0]; out[obase + 1] = a1 + ob[1]; }
        return;
    }

    if (blk < 82) {
        int b = blk - 66;
        int m = g_n[b] + 1, mm = m*m;
        float c0 = g_invconst[0], c1 = g_invconst[1];
        long base = EBASE + (long)b*Ee*2;
        for (int idx = mm*2 + tid; idx < 2048; idx += 256)
            out[base + idx] = (idx & 1) ? c1 : c0;
        return;
    }

    // ---- edges: block = (b, group of 16); warp handles 2 edges ----
    int id = blk - 82;               // 0..1023
    int b  = id >> 6;
    int e0 = (id & 63) * 16;
    int m = g_n[b] + 1, mm = m*m;
    if (e0 >= mm) return;

    #pragma unroll
    for (int u = 0; u < 4; u++) {
        int h = tid + u*256;
        float2 w = ((const float2*)eoW)[h];
        sWh[h] = __floats2half2_rn(w.x, w.y);
    }
    __syncthreads();

    int eA = e0 + wid*2;
    int eB = eA + 1;
    bool vA = eA < mm, vB = eB < mm;
    if (!vA) return;
    int eBc = vB ? eB : eA;
    int iA = eA / m, jA = eA - iA*m;
    int iB = eBc / m, jB = eBc - iB*m;
    const float4* ajA = (const float4*)&g_Aj[(long)(b*Kk + jA)*Hd];
    const float4* aiA = (const float4*)&g_Ai[(long)(b*Kk + iA)*Hd];
    const float4* ajB = (const float4*)&g_Aj[(long)(b*Kk + jB)*Hd];
    const float4* aiB = (const float4*)&g_Ai[(long)(b*Kk + iB)*Hd];

    float a0A = 0.f, a1A = 0.f, a0B = 0.f, a1B = 0.f;
    #pragma unroll
    for (int s = 0; s < 8; s++) {
        int q = s*32 + lane;
        float4 xA = ajA[q], yA = aiA[q];
        float4 xB = ajB[q], yB = aiB[q];
        uint4 wv = ((const uint4*)sWh)[q];
        const uint32_t wr[4] = {wv.x, wv.y, wv.z, wv.w};
        const float xa[4] = {xA.x, xA.y, xA.z, xA.w};
        const float ya[4] = {yA.x, yA.y, yA.z, yA.w};
        const float xb[4] = {xB.x, xB.y, xB.z, xB.w};
        const float yb[4] = {yB.x, yB.y, yB.z, yB.w};
        #pragma unroll
        for (int p = 0; p < 4; p++) {
            float2 w = __half22float2(*(const __half2*)&wr[p]);
            float tA = tanh_fast(xa[p] + ya[p]);
            float tB = tanh_fast(xb[p] + yb[p]);
            a0A = fmaf(tA, w.x, a0A); a1A = fmaf(tA, w.y, a1A);
            a0B = fmaf(tB, w.x, a0B); a1B = fmaf(tB, w.y, a1B);
        }
    }
    warp_reduce2(a0A, a1A);
    warp_reduce2(a0B, a1B);
    if (lane == 0) {
        long baseA = EBASE + ((long)b*Ee + eA)*2;
        out[baseA]     = a0A + eob[0];
        out[baseA + 1] = a1A + eob[1];
        if (vB) {
            long baseB = baseA + 2;
            out[baseB]     = a0B + eob[0];
            out[baseB + 1] = a1B + eob[1];
        }
    }
}

// ---------------------------------------------------------------------------
extern "C" void kernel_launch(void* const* d_in, const int* in_sizes, int n_in,
                              void* d_out, int out_size) {
    const float* seq   = (const float*)d_in[0];
    const int*   P     = (const int*)d_in[1];
    const float* nafW  = (const float*)d_in[2];
    const float* nafb  = (const float*)d_in[3];
    const float* clsW  = (const float*)d_in[4];
    const float* clsb  = (const float*)d_in[5];
    const float* clsoW = (const float*)d_in[6];
    const float* clsob = (const float*)d_in[7];
    const float* ndW   = (const float*)d_in[8];
    const float* ndb   = (const float*)d_in[9];
    const float* noW   = (const float*)d_in[10];
    const float* nob   = (const float*)d_in[11];
    const float* edW   = (const float*)d_in[12];
    const float* edb   = (const float*)d_in[13];
    const float* eoW   = (const float*)d_in[14];
    const float* eob   = (const float*)d_in[15];
    float* out = (float*)d_out;

    cudaFuncSetAttribute(k_gemm, cudaFuncAttributeMaxDynamicSharedMemorySize, 4*STAGE_B);

    k_prep<<<1553, 256>>>(seq, P, ndW, edW, edb, eoW, eob,
                          nafW, nafb, clsW, clsb);                          // idx 0
    k_gemm<<<dim3(NCAT/128, 512/64), 128, 4*STAGE_B>>>(ndb, edb);           // idx 1
    k_post<<<82 + 1024, 256>>>(clsoW, clsob, noW, nob, eoW, eob, out);      // idx 2
}